// round 15
// baseline (speedup 1.0000x reference)
#include <cuda_runtime.h>
#include <cuda_bf16.h>
#include <cuda_fp16.h>
#include <math.h>
#include <stdint.h>

#define NB 2
#define NS 2048
#define ND 1024
#define NH 16
#define HDIM 64
#define MROWS (NB*NS)
#define RWORDS (ND/2)          // 512 u32 words per 1024-elem fp16 row
#define NSPLIT 2
#define TILES_PER_SPLIT (NS / 64 / NSPLIT)   // 16

// ---- static scratch (no allocations allowed) ----
__device__ uint32_t g_inq[MROWS*RWORDS], g_ink[MROWS*RWORDS], g_inv[MROWS*RWORDS];
__device__ uint32_t g_w[4*ND*RWORDS];
__device__ uint32_t g_qf[NB*NH*NS*HDIM/2];
__device__ uint32_t g_kf[NB*NH*NS*HDIM/2];
__device__ uint32_t g_vf[NB*NH*NS*HDIM/2];
__device__ uint32_t g_cf[MROWS*RWORDS];
__device__ float g_pO[NSPLIT * 1024 * 64 * 64];
__device__ float g_pml[NSPLIT * 1024 * 64 * 2];

#define QSCALE 0.18033688011f      // 0.125 * log2(e)

#define MMAH16816(c, a, b) \
  asm volatile("mma.sync.aligned.m16n8k16.row.col.f32.f16.f16.f32 " \
    "{%0,%1,%2,%3}, {%4,%5,%6,%7}, {%8,%9}, {%0,%1,%2,%3};" \
    : "+f"((c)[0]), "+f"((c)[1]), "+f"((c)[2]), "+f"((c)[3]) \
    : "r"((a)[0]), "r"((a)[1]), "r"((a)[2]), "r"((a)[3]), \
      "r"((b)[0]), "r"((b)[1]))

__device__ __forceinline__ uint32_t pack_h2(float x, float y) {
    __half2 h = __floats2half2_rn(x, y);
    return *reinterpret_cast<uint32_t*>(&h);
}
__device__ __forceinline__ float ex2f(float x) {
    float y; asm("ex2.approx.ftz.f32 %0, %1;" : "=f"(y) : "f"(x)); return y;
}
__device__ __forceinline__ uint32_t smem_u32(const void* p) {
    uint32_t a;
    asm("{ .reg .u64 t; cvta.to.shared.u64 t, %1; cvt.u32.u64 %0, t; }" : "=r"(a) : "l"(p));
    return a;
}
__device__ __forceinline__ void ldsm_x4(uint32_t& r0, uint32_t& r1, uint32_t& r2, uint32_t& r3,
                                        uint32_t a) {
    asm volatile("ldmatrix.sync.aligned.m8n8.x4.shared.b16 {%0,%1,%2,%3}, [%4];"
                 : "=r"(r0), "=r"(r1), "=r"(r2), "=r"(r3) : "r"(a));
}
__device__ __forceinline__ void ldsm_x4_t(uint32_t& r0, uint32_t& r1, uint32_t& r2, uint32_t& r3,
                                          uint32_t a) {
    asm volatile("ldmatrix.sync.aligned.m8n8.x4.trans.shared.b16 {%0,%1,%2,%3}, [%4];"
                 : "=r"(r0), "=r"(r1), "=r"(r2), "=r"(r3) : "r"(a));
}
__device__ __forceinline__ void cp16(uint32_t dst, const void* src) {
    asm volatile("cp.async.cg.shared.global [%0], [%1], 16;" :: "r"(dst), "l"(src) : "memory");
}
__device__ __forceinline__ void cp_commit() {
    asm volatile("cp.async.commit_group;" ::: "memory");
}
template<int N> __device__ __forceinline__ void cp_wait() {
    asm volatile("cp.async.wait_group %0;" :: "n"(N) : "memory");
}

// ---------------------------------------------------------------------------
// fp32 -> fp16 single-plane converter, 7 tensors in one launch
// ---------------------------------------------------------------------------
struct CvtArgs {
    const float* s[7];
    uint32_t* pf[7];
    int cnt[7];
};

__global__ __launch_bounds__(256) void cvt_planes7(CvtArgs a)
{
    int z = blockIdx.z;
    int i = blockIdx.x * 256 + threadIdx.x;
    if (i >= a.cnt[z]) return;
    const float* s = a.s[z];
    float4 v0 = ((const float4*)s)[2 * i];
    float4 v1 = ((const float4*)s)[2 * i + 1];
    ((uint4*)a.pf[z])[i] = make_uint4(pack_h2(v0.x, v0.y), pack_h2(v0.z, v0.w),
                                      pack_h2(v1.x, v1.y), pack_h2(v1.z, v1.w));
}

// ---------------------------------------------------------------------------
// fp16 single-plane GEMM, 3-stage cp.async ring, 2 CTAs/SM.
// ---------------------------------------------------------------------------
struct GP {
    const uint32_t *Af, *Bf;
    const float* bias;
    float* C; uint32_t *Pf; float scale;
};
#define GSTAGE_B 20480

__global__ __launch_bounds__(256, 2) void gemm_planes(GP a0, GP a1, GP a2, int headmode)
{
    GP g = (blockIdx.z == 0) ? a0 : (blockIdx.z == 1) ? a1 : a2;
    extern __shared__ uint32_t smg[];
    const uint32_t sb = smem_u32(smg);

    const int tid = threadIdx.x;
    const int warp = tid >> 5;
    const int lane = tid & 31;
    const int r4 = lane >> 2, q4 = lane & 3;
    const int m0w = (warp >> 2) * 64;
    const int n0w = (warp & 3) * 32;
    const int mBase = blockIdx.y * 128;
    const int nBase = blockIdx.x * 128;

    const uint32_t* srcA = g.Af + (size_t)mBase * RWORDS;
    const uint32_t* srcB = g.Bf + (size_t)nBase * RWORDS;

    const uint32_t aOff = (uint32_t)((m0w + (lane & 15)) * 80 + (lane >> 4) * 16);
    const uint32_t bOff = (uint32_t)(10240 +
        (n0w + ((lane >> 4) & 1) * 8 + (lane & 7)) * 80 + ((lane >> 3) & 1) * 16);

    float acc[4][4][4];
#pragma unroll
    for (int mf = 0; mf < 4; mf++)
#pragma unroll
        for (int nf = 0; nf < 4; nf++)
#pragma unroll
            for (int c = 0; c < 4; c++) acc[mf][nf][c] = 0.f;

    auto issue = [&](int stage, int ch) {
#pragma unroll
        for (int it = 0; it < 4; it++) {
            int gi = tid + it * 256;
            int pl = gi >> 9, gg = gi & 511;
            int row = gg >> 2, seg = gg & 3;
            const uint32_t* src = (pl ? srcB : srcA) + (size_t)row * RWORDS + ch * 16 + seg * 4;
            uint32_t dst = sb + stage * GSTAGE_B + pl * 10240 + row * 80 + seg * 16;
            cp16(dst, src);
        }
        cp_commit();
    };

    issue(0, 0);
    issue(1, 1);
    issue(2, 2);

    int st = 0;
    for (int ch = 0; ch < 32; ch++) {
        if (ch <= 29) cp_wait<2>(); else if (ch == 30) cp_wait<1>(); else cp_wait<0>();
        __syncthreads();
        const uint32_t sBase = sb + st * GSTAGE_B;

#pragma unroll
        for (int ks = 0; ks < 2; ks++) {
            const uint32_t ko = ks * 32;
            uint32_t bfr[2][4];
#pragma unroll
            for (int nfp = 0; nfp < 2; nfp++)
                ldsm_x4(bfr[nfp][0], bfr[nfp][1], bfr[nfp][2], bfr[nfp][3],
                        sBase + bOff + nfp * 1280 + ko);
#pragma unroll
            for (int mf = 0; mf < 4; mf++) {
                uint32_t af[4];
                ldsm_x4(af[0], af[1], af[2], af[3], sBase + aOff + mf * 1280 + ko);
#pragma unroll
                for (int nfp = 0; nfp < 2; nfp++) {
                    MMAH16816(acc[mf][2 * nfp],     af, bfr[nfp]);
                    MMAH16816(acc[mf][2 * nfp + 1], af, bfr[nfp] + 2);
                }
            }
        }
        __syncthreads();
        if (ch + 3 < 32) issue(st, ch + 3);
        st = (st == 2) ? 0 : st + 1;
    }

#pragma unroll
    for (int nf = 0; nf < 4; nf++) {
        const int n = nBase + n0w + nf * 8 + q4 * 2;
        const float b0 = __ldg(g.bias + n);
        const float b1 = __ldg(g.bias + n + 1);
#pragma unroll
        for (int mf = 0; mf < 4; mf++) {
#pragma unroll
            for (int half = 0; half < 2; half++) {
                const int m = mBase + m0w + mf * 16 + r4 + half * 8;
                float v0 = (acc[mf][nf][half * 2] + b0) * g.scale;
                float v1 = (acc[mf][nf][half * 2 + 1] + b1) * g.scale;
                if (headmode) {
                    int b = m >> 11, s = m & (NS - 1);
                    int hh = n >> 6, e = n & 63;
                    size_t wo = (((size_t)((b * NH + hh) * NS + s)) * HDIM + e) >> 1;
                    g.Pf[wo] = pack_h2(v0, v1);
                } else {
                    *(float2*)(g.C + (size_t)m * ND + n) = make_float2(v0, v1);
                }
            }
        }
    }
}

// ---------------------------------------------------------------------------
// fp16 flash attention, split-KV x2, 3-stage cp.async ring, 3 CTAs/SM.
// Exact skip of O-rescale when warp-uniformly max unchanged.
// stage (bytes): Kf[0..9215] Vf[9216..18431]; 3 stages; maskF after.
// ---------------------------------------------------------------------------
#define ASTG 18432

__global__ __launch_bounds__(128, 3) void attn_mma(const uint32_t* __restrict__ qf,
                                                   const uint32_t* __restrict__ kf_,
                                                   const uint32_t* __restrict__ vf_,
                                                   const int* __restrict__ mask,
                                                   float* __restrict__ pO,
                                                   float* __restrict__ pml)
{
    extern __shared__ uint32_t dynsm[];
    const uint32_t sb = smem_u32(dynsm);
    float* sMkF = (float*)(dynsm + 3 * (ASTG / 4));
    uint32_t* sQ = dynsm;          // phase 1 only

    const int tid = threadIdx.x;
    const int warp = tid >> 5;
    const int lane = tid & 31;
    const int r4 = lane >> 2, q4 = lane & 3;
    const int qt = blockIdx.x;
    const int bh = blockIdx.y;
    const int sp = blockIdx.z;
    const int b = bh >> 4;
    const int ktBase = sp * TILES_PER_SPLIT;
    const size_t headW = (size_t)bh * NS * (HDIM / 2);

    {
        const uint32_t* pQ = qf + headW + (size_t)qt * 64 * 32;
#pragma unroll
        for (int it = 0; it < 4; it++) {
            int gi = tid + it * 128;
            int row = gi >> 3, w4 = (gi & 7) * 4;
            *(uint4*)(sQ + row * 36 + w4) = *(const uint4*)(pQ + row * 32 + w4);
        }
    }
    __syncthreads();
    uint32_t Qf[4][4];
#pragma unroll
    for (int kf = 0; kf < 4; kf++) {
        int off = (16 * warp + r4) * 36 + 8 * kf + q4;
        Qf[kf][0] = sQ[off];          Qf[kf][1] = sQ[off + 8 * 36];
        Qf[kf][2] = sQ[off + 4];      Qf[kf][3] = sQ[off + 8 * 36 + 4];
    }
    __syncthreads();

    const uint32_t* srcK = kf_ + headW;
    const uint32_t* srcV = vf_ + headW;
    auto issue = [&](int stage, int kt) {
#pragma unroll
        for (int it = 0; it < 8; it++) {
            int gi = tid + it * 128;
            int pl = gi >> 9, gg = gi & 511;
            int row = gg >> 3, seg = gg & 7;
            const uint32_t* src = (pl ? srcV : srcK) + (size_t)kt * 2048 + row * 32 + seg * 4;
            uint32_t dst = sb + stage * ASTG + pl * 9216 + row * 144 + seg * 16;
            cp16(dst, src);
        }
        cp_commit();
    };

    const uint32_t kBase = (uint32_t)((lane & 7) * 144 + (lane >> 3) * 16);
    const uint32_t vBase = (uint32_t)(9216 + (lane & 15) * 144 + (lane >> 4) * 16);

    float O[8][4];
    float mI0 = -INFINITY, mI1 = -INFINITY, lI0 = 0.f, lI1 = 0.f;
#pragma unroll
    for (int nf = 0; nf < 8; nf++)
#pragma unroll
        for (int c = 0; c < 4; c++) O[nf][c] = 0.f;

    const int* mrow = mask + (size_t)b * NS;
    float mkldF = (tid < 64 && mrow[ktBase * 64 + tid]) ? -9e9f : 0.f;

    issue(0, ktBase);
    issue(1, ktBase + 1);
    issue(2, ktBase + 2);

    int st = 0;
    for (int t = 0; t < TILES_PER_SPLIT; t++) {
        const int kt = ktBase + t;
        if (tid < 64) sMkF[tid] = mkldF;
        if (t <= TILES_PER_SPLIT - 3) cp_wait<2>();
        else if (t == TILES_PER_SPLIT - 2) cp_wait<1>();
        else cp_wait<0>();
        __syncthreads();
        const uint32_t sStage = sb + st * ASTG;

        float S[8][4];
#pragma unroll
        for (int nf = 0; nf < 8; nf++) {
            float2 ma = *(const float2*)(sMkF + 8 * nf + 2 * q4);
            S[nf][0] = ma.x; S[nf][1] = ma.y;
            S[nf][2] = ma.x; S[nf][3] = ma.y;
        }
#pragma unroll
        for (int nf = 0; nf < 8; nf++) {
            uint32_t kb[4], kb2[4];
            ldsm_x4(kb[0], kb[1], kb[2], kb[3], sStage + kBase + (uint32_t)(nf * 1152));
            ldsm_x4(kb2[0], kb2[1], kb2[2], kb2[3],
                    sStage + kBase + (uint32_t)(nf * 1152 + 64));
            MMAH16816(S[nf], Qf[0], kb);
            MMAH16816(S[nf], Qf[1], kb + 2);
            MMAH16816(S[nf], Qf[2], kb2);
            MMAH16816(S[nf], Qf[3], kb2 + 2);
        }

        float mt0 = -INFINITY, mt1 = -INFINITY;
#pragma unroll
        for (int nf = 0; nf < 8; nf++) {
            mt0 = fmaxf(mt0, fmaxf(S[nf][0], S[nf][1]));
            mt1 = fmaxf(mt1, fmaxf(S[nf][2], S[nf][3]));
        }
        mt0 = fmaxf(mt0, __shfl_xor_sync(0xffffffffu, mt0, 1));
        mt0 = fmaxf(mt0, __shfl_xor_sync(0xffffffffu, mt0, 2));
        mt1 = fmaxf(mt1, __shfl_xor_sync(0xffffffffu, mt1, 1));
        mt1 = fmaxf(mt1, __shfl_xor_sync(0xffffffffu, mt1, 2));

        float mN0 = fmaxf(mI0, mt0), mN1 = fmaxf(mI1, mt1);
        // exact warp-uniform skip: f==1 iff max unchanged
        bool nochg = (mN0 == mI0) && (mN1 == mI1);
        if (!__all_sync(0xffffffffu, nochg)) {
            float f0 = ex2f(mI0 - mN0), f1 = ex2f(mI1 - mN1);
            lI0 *= f0; lI1 *= f1;
#pragma unroll
            for (int nf = 0; nf < 8; nf++) {
                O[nf][0] *= f0; O[nf][1] *= f0;
                O[nf][2] *= f1; O[nf][3] *= f1;
            }
            mI0 = mN0; mI1 = mN1;
        }
        float rs0 = 0.f, rs1 = 0.f;
#pragma unroll
        for (int nf = 0; nf < 8; nf++) {
            S[nf][0] = ex2f(S[nf][0] - mI0);
            S[nf][1] = ex2f(S[nf][1] - mI0);
            S[nf][2] = ex2f(S[nf][2] - mI1);
            S[nf][3] = ex2f(S[nf][3] - mI1);
            rs0 += S[nf][0] + S[nf][1];
            rs1 += S[nf][2] + S[nf][3];
        }
        rs0 += __shfl_xor_sync(0xffffffffu, rs0, 1);
        rs0 += __shfl_xor_sync(0xffffffffu, rs0, 2);
        rs1 += __shfl_xor_sync(0xffffffffu, rs1, 1);
        rs1 += __shfl_xor_sync(0xffffffffu, rs1, 2);
        lI0 += rs0;
        lI1 += rs1;

        uint32_t Pa[4][4];
#pragma unroll
        for (int kf = 0; kf < 4; kf++) {
            Pa[kf][0] = pack_h2(S[2*kf][0],     S[2*kf][1]);
            Pa[kf][1] = pack_h2(S[2*kf][2],     S[2*kf][3]);
            Pa[kf][2] = pack_h2(S[2*kf + 1][0], S[2*kf + 1][1]);
            Pa[kf][3] = pack_h2(S[2*kf + 1][2], S[2*kf + 1][3]);
        }

#pragma unroll
        for (int kf = 0; kf < 4; kf++) {
            uint32_t abase = sStage + vBase + (uint32_t)(kf * 2304);
#pragma unroll
            for (int nfp = 0; nfp < 4; nfp++) {
                uint32_t vv[4];
                ldsm_x4_t(vv[0], vv[1], vv[2], vv[3], abase + nfp * 32);
                MMAH16816(O[2 * nfp],     Pa[kf], vv);
                MMAH16816(O[2 * nfp + 1], Pa[kf], vv + 2);
            }
        }

        __syncthreads();
        if (t + 3 < TILES_PER_SPLIT) issue(st, kt + 3);
        if (t + 1 < TILES_PER_SPLIT && tid < 64)
            mkldF = mrow[(kt + 1) * 64 + tid] ? -9e9f : 0.f;
        st = (st == 2) ? 0 : st + 1;
    }

    const int tile = bh * 32 + qt;
    float* po = pO + (size_t)sp * (1024 * 64 * 64) + (size_t)tile * (64 * 64);
    float* pm = pml + (size_t)sp * (1024 * 64 * 2) + (size_t)tile * (64 * 2);
    const int row0 = 16 * warp + r4;
#pragma unroll
    for (int nf = 0; nf < 8; nf++) {
        *(float2*)(po + row0 * 64 + 8 * nf + 2 * q4)       = make_float2(O[nf][0], O[nf][1]);
        *(float2*)(po + (row0 + 8) * 64 + 8 * nf + 2 * q4) = make_float2(O[nf][2], O[nf][3]);
    }
    if (q4 == 0) {
        *(float2*)(pm + row0 * 2)       = make_float2(mI0, lI0);
        *(float2*)(pm + (row0 + 8) * 2) = make_float2(mI1, lI1);
    }
}

// ---------------------------------------------------------------------------
// Combine split-KV partials -> ctx fp16 plane [b][s][h*64+e]
// ---------------------------------------------------------------------------
__global__ __launch_bounds__(256) void attn_combine(const float* __restrict__ pO,
                                                    const float* __restrict__ pml,
                                                    uint32_t* __restrict__ cf_out)
{
    const int gid = blockIdx.x * 256 + threadIdx.x;
    const int grp = gid & 3;
    const int rowg = gid >> 2;
    const int r = rowg & 63;
    const int tile = rowg >> 6;
    const int qt = tile & 31, bh = tile >> 5;
    const size_t SPO = (size_t)1024 * 64 * 64;
    const size_t SPM = (size_t)1024 * 64 * 2;
    const size_t obase = (size_t)rowg * 64 + grp * 16;
    const size_t mlbase = (size_t)rowg * 2;

    float2 ml0 = *(const float2*)(pml + mlbase);
    float2 ml1 = *(const float2*)(pml + SPM + mlbase);
    float m = fmaxf(ml0.x, ml1.x);
    float f0 = ex2f(ml0.x - m), f1 = ex2f(ml1.x - m);
    float inv = 1.f / (ml0.y * f0 + ml1.y * f1);
    f0 *= inv; f1 *= inv;

    uint32_t w[8];
#pragma unroll
    for (int c4 = 0; c4 < 4; c4++) {
        float4 a = *(const float4*)(pO + obase + c4 * 4);
        float4 bb = *(const float4*)(pO + SPO + obase + c4 * 4);
        w[c4 * 2]     = pack_h2(a.x * f0 + bb.x * f1, a.y * f0 + bb.y * f1);
        w[c4 * 2 + 1] = pack_h2(a.z * f0 + bb.z * f1, a.w * f0 + bb.w * f1);
    }

    const int b = bh >> 4, h = bh & 15;
    const int srow = qt * 64 + r;
    const size_t wo = (((size_t)(b * NS + srow)) * ND + h * HDIM + grp * 16) >> 1;
    *(uint4*)(cf_out + wo)     = make_uint4(w[0], w[1], w[2], w[3]);
    *(uint4*)(cf_out + wo + 4) = make_uint4(w[4], w[5], w[6], w[7]);
}

extern "C" void kernel_launch(void* const* d_in, const int* in_sizes, int n_in,
                              void* d_out, int out_size)
{
    const float* q  = (const float*)d_in[0];
    const float* k  = (const float*)d_in[1];
    const float* v  = (const float*)d_in[2];
    const int* mask = (const int*)d_in[3];
    const float* Wq = (const float*)d_in[4];
    const float* bq = (const float*)d_in[5];
    const float* Wk = (const float*)d_in[6];
    const float* bk = (const float*)d_in[7];
    const float* Wv = (const float*)d_in[8];
    const float* bv = (const float*)d_in[9];
    const float* Wo = (const float*)d_in[10];
    const float* bo = (const float*)d_in[11];
    float* out = (float*)d_out;

    uint32_t *inq_d, *ink_d, *inv_d, *w_d;
    uint32_t *qf_d, *kf_d, *vf_d, *cf_d;
    float *pO_d, *pml_d;
    cudaGetSymbolAddress((void**)&inq_d, g_inq);
    cudaGetSymbolAddress((void**)&ink_d, g_ink);
    cudaGetSymbolAddress((void**)&inv_d, g_inv);
    cudaGetSymbolAddress((void**)&w_d, g_w);
    cudaGetSymbolAddress((void**)&qf_d, g_qf);
    cudaGetSymbolAddress((void**)&kf_d, g_kf);
    cudaGetSymbolAddress((void**)&vf_d, g_vf);
    cudaGetSymbolAddress((void**)&cf_d, g_cf);
    cudaGetSymbolAddress((void**)&pO_d, g_pO);
    cudaGetSymbolAddress((void**)&pml_d, g_pml);

    const int WSTRIDE = ND * RWORDS;
    const int NIN = MROWS * ND / 8;
    const int NW  = ND * ND / 8;

    CvtArgs ca;
    ca.s[0] = q;  ca.pf[0] = inq_d;            ca.cnt[0] = NIN;
    ca.s[1] = k;  ca.pf[1] = ink_d;            ca.cnt[1] = NIN;
    ca.s[2] = v;  ca.pf[2] = inv_d;            ca.cnt[2] = NIN;
    ca.s[3] = Wq; ca.pf[3] = w_d;              ca.cnt[3] = NW;
    ca.s[4] = Wk; ca.pf[4] = w_d + WSTRIDE;    ca.cnt[4] = NW;
    ca.s[5] = Wv; ca.pf[5] = w_d + 2*WSTRIDE;  ca.cnt[5] = NW;
    ca.s[6] = Wo; ca.pf[6] = w_d + 3*WSTRIDE;  ca.cnt[6] = NW;
    cvt_planes7<<<dim3((NIN + 255) / 256, 1, 7), 256>>>(ca);

    const int smem_gemm = 3 * GSTAGE_B;                 // 61440
    cudaFuncSetAttribute(gemm_planes, cudaFuncAttributeMaxDynamicSharedMemorySize, smem_gemm);
    const int smem_attn = 3 * ASTG + 64 * 4;            // 55552
    cudaFuncSetAttribute(attn_mma, cudaFuncAttributeMaxDynamicSharedMemorySize, smem_attn);

    GP aq{inq_d, w_d, bq, nullptr, qf_d, QSCALE};
    GP ak{ink_d, w_d + WSTRIDE, bk, nullptr, kf_d, 1.f};
    GP av{inv_d, w_d + 2 * WSTRIDE, bv, nullptr, vf_d, 1.f};
    gemm_planes<<<dim3(ND / 128, MROWS / 128, 3), 256, smem_gemm>>>(aq, ak, av, 1);

    attn_mma<<<dim3(NS / 64, NB * NH, NSPLIT), 128, smem_attn>>>(
        qf_d, kf_d, vf_d, mask, pO_d, pml_d);

    attn_combine<<<1024, 256>>>(pO_d, pml_d, cf_d);

    GP ao{cf_d, w_d + 3 * WSTRIDE, bo, out, nullptr, 1.f};
    gemm_planes<<<dim3(ND / 128, MROWS / 128, 1), 256, smem_gemm>>>(ao, ao, ao, 0);
}

// round 16
// speedup vs baseline: 1.0326x; 1.0326x over previous
#include <cuda_runtime.h>
#include <cuda_bf16.h>
#include <cuda_fp16.h>
#include <math.h>
#include <stdint.h>

#define NB 2
#define NS 2048
#define ND 1024
#define NH 16
#define HDIM 64
#define MROWS (NB*NS)
#define RWORDS (ND/2)          // 512 u32 words per 1024-elem fp16 row
#define NSPLIT 2
#define TILES_PER_SPLIT (NS / 64 / NSPLIT)   // 16

// ---- static scratch (no allocations allowed) ----
__device__ uint32_t g_inq[MROWS*RWORDS], g_ink[MROWS*RWORDS], g_inv[MROWS*RWORDS];
__device__ uint32_t g_w[4*ND*RWORDS];
__device__ uint32_t g_qf[NB*NH*NS*HDIM/2];
__device__ uint32_t g_kf[NB*NH*NS*HDIM/2];
__device__ uint32_t g_vf[NB*NH*NS*HDIM/2];
__device__ uint32_t g_cf[MROWS*RWORDS];
__device__ float g_pO[NSPLIT * 1024 * 64 * 64];
__device__ float g_pml[NSPLIT * 1024 * 64 * 2];

#define QSCALE 0.18033688011f      // 0.125 * log2(e)

#define MMAH16816(c, a, b) \
  asm volatile("mma.sync.aligned.m16n8k16.row.col.f32.f16.f16.f32 " \
    "{%0,%1,%2,%3}, {%4,%5,%6,%7}, {%8,%9}, {%0,%1,%2,%3};" \
    : "+f"((c)[0]), "+f"((c)[1]), "+f"((c)[2]), "+f"((c)[3]) \
    : "r"((a)[0]), "r"((a)[1]), "r"((a)[2]), "r"((a)[3]), \
      "r"((b)[0]), "r"((b)[1]))

__device__ __forceinline__ uint32_t pack_h2(float x, float y) {
    __half2 h = __floats2half2_rn(x, y);
    return *reinterpret_cast<uint32_t*>(&h);
}
__device__ __forceinline__ float ex2f(float x) {
    float y; asm("ex2.approx.ftz.f32 %0, %1;" : "=f"(y) : "f"(x)); return y;
}
__device__ __forceinline__ uint32_t smem_u32(const void* p) {
    uint32_t a;
    asm("{ .reg .u64 t; cvta.to.shared.u64 t, %1; cvt.u32.u64 %0, t; }" : "=r"(a) : "l"(p));
    return a;
}
__device__ __forceinline__ void ldsm_x4(uint32_t& r0, uint32_t& r1, uint32_t& r2, uint32_t& r3,
                                        uint32_t a) {
    asm volatile("ldmatrix.sync.aligned.m8n8.x4.shared.b16 {%0,%1,%2,%3}, [%4];"
                 : "=r"(r0), "=r"(r1), "=r"(r2), "=r"(r3) : "r"(a));
}
__device__ __forceinline__ void ldsm_x4_t(uint32_t& r0, uint32_t& r1, uint32_t& r2, uint32_t& r3,
                                          uint32_t a) {
    asm volatile("ldmatrix.sync.aligned.m8n8.x4.trans.shared.b16 {%0,%1,%2,%3}, [%4];"
                 : "=r"(r0), "=r"(r1), "=r"(r2), "=r"(r3) : "r"(a));
}
__device__ __forceinline__ void cp16(uint32_t dst, const void* src) {
    asm volatile("cp.async.cg.shared.global [%0], [%1], 16;" :: "r"(dst), "l"(src) : "memory");
}
__device__ __forceinline__ void cp_commit() {
    asm volatile("cp.async.commit_group;" ::: "memory");
}
template<int N> __device__ __forceinline__ void cp_wait() {
    asm volatile("cp.async.wait_group %0;" :: "n"(N) : "memory");
}

// ---------------------------------------------------------------------------
// fp32 -> fp16 single-plane converter, 7 tensors in one launch
// ---------------------------------------------------------------------------
struct CvtArgs {
    const float* s[7];
    uint32_t* pf[7];
    int cnt[7];
};

__global__ __launch_bounds__(256) void cvt_planes7(CvtArgs a)
{
    int z = blockIdx.z;
    int i = blockIdx.x * 256 + threadIdx.x;
    if (i >= a.cnt[z]) return;
    const float* s = a.s[z];
    float4 v0 = ((const float4*)s)[2 * i];
    float4 v1 = ((const float4*)s)[2 * i + 1];
    ((uint4*)a.pf[z])[i] = make_uint4(pack_h2(v0.x, v0.y), pack_h2(v0.z, v0.w),
                                      pack_h2(v1.x, v1.y), pack_h2(v1.z, v1.w));
}

// ---------------------------------------------------------------------------
// fp16 single-plane GEMM, 3-stage cp.async ring, 2 CTAs/SM (unchanged R15)
// ---------------------------------------------------------------------------
struct GP {
    const uint32_t *Af, *Bf;
    const float* bias;
    float* C; uint32_t *Pf; float scale;
};
#define GSTAGE_B 20480

__global__ __launch_bounds__(256, 2) void gemm_planes(GP a0, GP a1, GP a2, int headmode)
{
    GP g = (blockIdx.z == 0) ? a0 : (blockIdx.z == 1) ? a1 : a2;
    extern __shared__ uint32_t smg[];
    const uint32_t sb = smem_u32(smg);

    const int tid = threadIdx.x;
    const int warp = tid >> 5;
    const int lane = tid & 31;
    const int r4 = lane >> 2, q4 = lane & 3;
    const int m0w = (warp >> 2) * 64;
    const int n0w = (warp & 3) * 32;
    const int mBase = blockIdx.y * 128;
    const int nBase = blockIdx.x * 128;

    const uint32_t* srcA = g.Af + (size_t)mBase * RWORDS;
    const uint32_t* srcB = g.Bf + (size_t)nBase * RWORDS;

    const uint32_t aOff = (uint32_t)((m0w + (lane & 15)) * 80 + (lane >> 4) * 16);
    const uint32_t bOff = (uint32_t)(10240 +
        (n0w + ((lane >> 4) & 1) * 8 + (lane & 7)) * 80 + ((lane >> 3) & 1) * 16);

    float acc[4][4][4];
#pragma unroll
    for (int mf = 0; mf < 4; mf++)
#pragma unroll
        for (int nf = 0; nf < 4; nf++)
#pragma unroll
            for (int c = 0; c < 4; c++) acc[mf][nf][c] = 0.f;

    auto issue = [&](int stage, int ch) {
#pragma unroll
        for (int it = 0; it < 4; it++) {
            int gi = tid + it * 256;
            int pl = gi >> 9, gg = gi & 511;
            int row = gg >> 2, seg = gg & 3;
            const uint32_t* src = (pl ? srcB : srcA) + (size_t)row * RWORDS + ch * 16 + seg * 4;
            uint32_t dst = sb + stage * GSTAGE_B + pl * 10240 + row * 80 + seg * 16;
            cp16(dst, src);
        }
        cp_commit();
    };

    issue(0, 0);
    issue(1, 1);
    issue(2, 2);

    int st = 0;
    for (int ch = 0; ch < 32; ch++) {
        if (ch <= 29) cp_wait<2>(); else if (ch == 30) cp_wait<1>(); else cp_wait<0>();
        __syncthreads();
        const uint32_t sBase = sb + st * GSTAGE_B;

#pragma unroll
        for (int ks = 0; ks < 2; ks++) {
            const uint32_t ko = ks * 32;
            uint32_t bfr[2][4];
#pragma unroll
            for (int nfp = 0; nfp < 2; nfp++)
                ldsm_x4(bfr[nfp][0], bfr[nfp][1], bfr[nfp][2], bfr[nfp][3],
                        sBase + bOff + nfp * 1280 + ko);
#pragma unroll
            for (int mf = 0; mf < 4; mf++) {
                uint32_t af[4];
                ldsm_x4(af[0], af[1], af[2], af[3], sBase + aOff + mf * 1280 + ko);
#pragma unroll
                for (int nfp = 0; nfp < 2; nfp++) {
                    MMAH16816(acc[mf][2 * nfp],     af, bfr[nfp]);
                    MMAH16816(acc[mf][2 * nfp + 1], af, bfr[nfp] + 2);
                }
            }
        }
        __syncthreads();
        if (ch + 3 < 32) issue(st, ch + 3);
        st = (st == 2) ? 0 : st + 1;
    }

#pragma unroll
    for (int nf = 0; nf < 4; nf++) {
        const int n = nBase + n0w + nf * 8 + q4 * 2;
        const float b0 = __ldg(g.bias + n);
        const float b1 = __ldg(g.bias + n + 1);
#pragma unroll
        for (int mf = 0; mf < 4; mf++) {
#pragma unroll
            for (int half = 0; half < 2; half++) {
                const int m = mBase + m0w + mf * 16 + r4 + half * 8;
                float v0 = (acc[mf][nf][half * 2] + b0) * g.scale;
                float v1 = (acc[mf][nf][half * 2 + 1] + b1) * g.scale;
                if (headmode) {
                    int b = m >> 11, s = m & (NS - 1);
                    int hh = n >> 6, e = n & 63;
                    size_t wo = (((size_t)((b * NH + hh) * NS + s)) * HDIM + e) >> 1;
                    g.Pf[wo] = pack_h2(v0, v1);
                } else {
                    *(float2*)(g.C + (size_t)m * ND + n) = make_float2(v0, v1);
                }
            }
        }
    }
}

// ---------------------------------------------------------------------------
// fp16 flash attention, split-KV x2: BQ=128, 256 threads (8 warps), 2 CTAs/SM
// -> 16 warps/SM for issue-slot utilization. Per-warp work identical to R15.
// stage (bytes): Kf[0..9215] Vf[9216..18431]; 3 stages; maskF after.
// ---------------------------------------------------------------------------
#define ASTG 18432

__global__ __launch_bounds__(256, 2) void attn_mma(const uint32_t* __restrict__ qf,
                                                   const uint32_t* __restrict__ kf_,
                                                   const uint32_t* __restrict__ vf_,
                                                   const int* __restrict__ mask,
                                                   float* __restrict__ pO,
                                                   float* __restrict__ pml)
{
    extern __shared__ uint32_t dynsm[];
    const uint32_t sb = smem_u32(dynsm);
    float* sMkF = (float*)(dynsm + 3 * (ASTG / 4));
    uint32_t* sQ = dynsm;          // phase 1 only: 128 rows x 36 words (18KB)

    const int tid = threadIdx.x;
    const int warp = tid >> 5;     // 0..7
    const int lane = tid & 31;
    const int r4 = lane >> 2, q4 = lane & 3;
    const int qt = blockIdx.x;     // 0..15 (128-row q tiles)
    const int bh = blockIdx.y;     // 0..31
    const int sp = blockIdx.z;     // 0..1
    const int b = bh >> 4;
    const int ktBase = sp * TILES_PER_SPLIT;
    const size_t headW = (size_t)bh * NS * (HDIM / 2);

    // ---- Phase 1: stage Q (fp16 plane, 128 rows), load persistent A-frags ----
    {
        const uint32_t* pQ = qf + headW + (size_t)qt * 128 * 32;
#pragma unroll
        for (int it = 0; it < 4; it++) {
            int gi = tid + it * 256;       // 0..1023
            int row = gi >> 3, w4 = (gi & 7) * 4;
            *(uint4*)(sQ + row * 36 + w4) = *(const uint4*)(pQ + row * 32 + w4);
        }
    }
    __syncthreads();
    uint32_t Qf[4][4];
#pragma unroll
    for (int kf = 0; kf < 4; kf++) {
        int off = (16 * warp + r4) * 36 + 8 * kf + q4;
        Qf[kf][0] = sQ[off];          Qf[kf][1] = sQ[off + 8 * 36];
        Qf[kf][2] = sQ[off + 4];      Qf[kf][3] = sQ[off + 8 * 36 + 4];
    }
    __syncthreads();

    const uint32_t* srcK = kf_ + headW;
    const uint32_t* srcV = vf_ + headW;
    auto issue = [&](int stage, int kt) {
#pragma unroll
        for (int it = 0; it < 4; it++) {
            int gi = tid + it * 256;       // 0..1023
            int pl = gi >> 9, gg = gi & 511;
            int row = gg >> 3, seg = gg & 7;
            const uint32_t* src = (pl ? srcV : srcK) + (size_t)kt * 2048 + row * 32 + seg * 4;
            uint32_t dst = sb + stage * ASTG + pl * 9216 + row * 144 + seg * 16;
            cp16(dst, src);
        }
        cp_commit();
    };

    const uint32_t kBase = (uint32_t)((lane & 7) * 144 + (lane >> 3) * 16);
    const uint32_t vBase = (uint32_t)(9216 + (lane & 15) * 144 + (lane >> 4) * 16);

    float O[8][4];
    float mI0 = -INFINITY, mI1 = -INFINITY, lI0 = 0.f, lI1 = 0.f;
#pragma unroll
    for (int nf = 0; nf < 8; nf++)
#pragma unroll
        for (int c = 0; c < 4; c++) O[nf][c] = 0.f;

    const int* mrow = mask + (size_t)b * NS;
    float mkldF = (tid < 64 && mrow[ktBase * 64 + tid]) ? -9e9f : 0.f;

    issue(0, ktBase);
    issue(1, ktBase + 1);
    issue(2, ktBase + 2);

    int st = 0;
    for (int t = 0; t < TILES_PER_SPLIT; t++) {
        const int kt = ktBase + t;
        if (tid < 64) sMkF[tid] = mkldF;
        if (t <= TILES_PER_SPLIT - 3) cp_wait<2>();
        else if (t == TILES_PER_SPLIT - 2) cp_wait<1>();
        else cp_wait<0>();
        __syncthreads();
        const uint32_t sStage = sb + st * ASTG;

        float S[8][4];
#pragma unroll
        for (int nf = 0; nf < 8; nf++) {
            float2 ma = *(const float2*)(sMkF + 8 * nf + 2 * q4);
            S[nf][0] = ma.x; S[nf][1] = ma.y;
            S[nf][2] = ma.x; S[nf][3] = ma.y;
        }
#pragma unroll
        for (int nf = 0; nf < 8; nf++) {
            uint32_t kb[4], kb2[4];
            ldsm_x4(kb[0], kb[1], kb[2], kb[3], sStage + kBase + (uint32_t)(nf * 1152));
            ldsm_x4(kb2[0], kb2[1], kb2[2], kb2[3],
                    sStage + kBase + (uint32_t)(nf * 1152 + 64));
            MMAH16816(S[nf], Qf[0], kb);
            MMAH16816(S[nf], Qf[1], kb + 2);
            MMAH16816(S[nf], Qf[2], kb2);
            MMAH16816(S[nf], Qf[3], kb2 + 2);
        }

        float mt0 = -INFINITY, mt1 = -INFINITY;
#pragma unroll
        for (int nf = 0; nf < 8; nf++) {
            mt0 = fmaxf(mt0, fmaxf(S[nf][0], S[nf][1]));
            mt1 = fmaxf(mt1, fmaxf(S[nf][2], S[nf][3]));
        }
        mt0 = fmaxf(mt0, __shfl_xor_sync(0xffffffffu, mt0, 1));
        mt0 = fmaxf(mt0, __shfl_xor_sync(0xffffffffu, mt0, 2));
        mt1 = fmaxf(mt1, __shfl_xor_sync(0xffffffffu, mt1, 1));
        mt1 = fmaxf(mt1, __shfl_xor_sync(0xffffffffu, mt1, 2));

        float mN0 = fmaxf(mI0, mt0), mN1 = fmaxf(mI1, mt1);
        bool nochg = (mN0 == mI0) && (mN1 == mI1);
        if (!__all_sync(0xffffffffu, nochg)) {
            float f0 = ex2f(mI0 - mN0), f1 = ex2f(mI1 - mN1);
            lI0 *= f0; lI1 *= f1;
#pragma unroll
            for (int nf = 0; nf < 8; nf++) {
                O[nf][0] *= f0; O[nf][1] *= f0;
                O[nf][2] *= f1; O[nf][3] *= f1;
            }
            mI0 = mN0; mI1 = mN1;
        }
        float rs0 = 0.f, rs1 = 0.f;
#pragma unroll
        for (int nf = 0; nf < 8; nf++) {
            S[nf][0] = ex2f(S[nf][0] - mI0);
            S[nf][1] = ex2f(S[nf][1] - mI0);
            S[nf][2] = ex2f(S[nf][2] - mI1);
            S[nf][3] = ex2f(S[nf][3] - mI1);
            rs0 += S[nf][0] + S[nf][1];
            rs1 += S[nf][2] + S[nf][3];
        }
        rs0 += __shfl_xor_sync(0xffffffffu, rs0, 1);
        rs0 += __shfl_xor_sync(0xffffffffu, rs0, 2);
        rs1 += __shfl_xor_sync(0xffffffffu, rs1, 1);
        rs1 += __shfl_xor_sync(0xffffffffu, rs1, 2);
        lI0 += rs0;
        lI1 += rs1;

        uint32_t Pa[4][4];
#pragma unroll
        for (int kf = 0; kf < 4; kf++) {
            Pa[kf][0] = pack_h2(S[2*kf][0],     S[2*kf][1]);
            Pa[kf][1] = pack_h2(S[2*kf][2],     S[2*kf][3]);
            Pa[kf][2] = pack_h2(S[2*kf + 1][0], S[2*kf + 1][1]);
            Pa[kf][3] = pack_h2(S[2*kf + 1][2], S[2*kf + 1][3]);
        }

#pragma unroll
        for (int kf = 0; kf < 4; kf++) {
            uint32_t abase = sStage + vBase + (uint32_t)(kf * 2304);
#pragma unroll
            for (int nfp = 0; nfp < 4; nfp++) {
                uint32_t vv[4];
                ldsm_x4_t(vv[0], vv[1], vv[2], vv[3], abase + nfp * 32);
                MMAH16816(O[2 * nfp],     Pa[kf], vv);
                MMAH16816(O[2 * nfp + 1], Pa[kf], vv + 2);
            }
        }

        __syncthreads();
        if (t + 3 < TILES_PER_SPLIT) issue(st, kt + 3);
        if (t + 1 < TILES_PER_SPLIT && tid < 64)
            mkldF = mrow[(kt + 1) * 64 + tid] ? -9e9f : 0.f;
        st = (st == 2) ? 0 : st + 1;
    }

    // ---- write UNNORMALIZED partials + (m,l); 64-row tile granularity ----
    const int row0 = 16 * warp + r4;              // 0..127 within q-tile
    const int srow0 = qt * 128 + row0;
#pragma unroll
    for (int half = 0; half < 2; half++) {
        const int srow = srow0 + half * 8;
        const int tile = bh * 32 + (srow >> 6);
        const int rin = srow & 63;
        float* po = pO + (size_t)sp * (1024 * 64 * 64) + (size_t)tile * (64 * 64);
        float* pm = pml + (size_t)sp * (1024 * 64 * 2) + (size_t)tile * (64 * 2);
#pragma unroll
        for (int nf = 0; nf < 8; nf++)
            *(float2*)(po + rin * 64 + 8 * nf + 2 * q4) =
                (half == 0) ? make_float2(O[nf][0], O[nf][1])
                            : make_float2(O[nf][2], O[nf][3]);
        if (q4 == 0)
            *(float2*)(pm + rin * 2) =
                (half == 0) ? make_float2(mI0, lI0) : make_float2(mI1, lI1);
    }
}

// ---------------------------------------------------------------------------
// Combine split-KV partials -> ctx fp16 plane [b][s][h*64+e] (unchanged)
// ---------------------------------------------------------------------------
__global__ __launch_bounds__(256) void attn_combine(const float* __restrict__ pO,
                                                    const float* __restrict__ pml,
                                                    uint32_t* __restrict__ cf_out)
{
    const int gid = blockIdx.x * 256 + threadIdx.x;
    const int grp = gid & 3;
    const int rowg = gid >> 2;
    const int r = rowg & 63;
    const int tile = rowg >> 6;
    const int qt = tile & 31, bh = tile >> 5;
    const size_t SPO = (size_t)1024 * 64 * 64;
    const size_t SPM = (size_t)1024 * 64 * 2;
    const size_t obase = (size_t)rowg * 64 + grp * 16;
    const size_t mlbase = (size_t)rowg * 2;

    float2 ml0 = *(const float2*)(pml + mlbase);
    float2 ml1 = *(const float2*)(pml + SPM + mlbase);
    float m = fmaxf(ml0.x, ml1.x);
    float f0 = ex2f(ml0.x - m), f1 = ex2f(ml1.x - m);
    float inv = 1.f / (ml0.y * f0 + ml1.y * f1);
    f0 *= inv; f1 *= inv;

    uint32_t w[8];
#pragma unroll
    for (int c4 = 0; c4 < 4; c4++) {
        float4 a = *(const float4*)(pO + obase + c4 * 4);
        float4 bb = *(const float4*)(pO + SPO + obase + c4 * 4);
        w[c4 * 2]     = pack_h2(a.x * f0 + bb.x * f1, a.y * f0 + bb.y * f1);
        w[c4 * 2 + 1] = pack_h2(a.z * f0 + bb.z * f1, a.w * f0 + bb.w * f1);
    }

    const int b = bh >> 4, h = bh & 15;
    const int srow = qt * 64 + r;
    const size_t wo = (((size_t)(b * NS + srow)) * ND + h * HDIM + grp * 16) >> 1;
    *(uint4*)(cf_out + wo)     = make_uint4(w[0], w[1], w[2], w[3]);
    *(uint4*)(cf_out + wo + 4) = make_uint4(w[4], w[5], w[6], w[7]);
}

extern "C" void kernel_launch(void* const* d_in, const int* in_sizes, int n_in,
                              void* d_out, int out_size)
{
    const float* q  = (const float*)d_in[0];
    const float* k  = (const float*)d_in[1];
    const float* v  = (const float*)d_in[2];
    const int* mask = (const int*)d_in[3];
    const float* Wq = (const float*)d_in[4];
    const float* bq = (const float*)d_in[5];
    const float* Wk = (const float*)d_in[6];
    const float* bk = (const float*)d_in[7];
    const float* Wv = (const float*)d_in[8];
    const float* bv = (const float*)d_in[9];
    const float* Wo = (const float*)d_in[10];
    const float* bo = (const float*)d_in[11];
    float* out = (float*)d_out;

    uint32_t *inq_d, *ink_d, *inv_d, *w_d;
    uint32_t *qf_d, *kf_d, *vf_d, *cf_d;
    float *pO_d, *pml_d;
    cudaGetSymbolAddress((void**)&inq_d, g_inq);
    cudaGetSymbolAddress((void**)&ink_d, g_ink);
    cudaGetSymbolAddress((void**)&inv_d, g_inv);
    cudaGetSymbolAddress((void**)&w_d, g_w);
    cudaGetSymbolAddress((void**)&qf_d, g_qf);
    cudaGetSymbolAddress((void**)&kf_d, g_kf);
    cudaGetSymbolAddress((void**)&vf_d, g_vf);
    cudaGetSymbolAddress((void**)&cf_d, g_cf);
    cudaGetSymbolAddress((void**)&pO_d, g_pO);
    cudaGetSymbolAddress((void**)&pml_d, g_pml);

    const int WSTRIDE = ND * RWORDS;
    const int NIN = MROWS * ND / 8;
    const int NW  = ND * ND / 8;

    CvtArgs ca;
    ca.s[0] = q;  ca.pf[0] = inq_d;            ca.cnt[0] = NIN;
    ca.s[1] = k;  ca.pf[1] = ink_d;            ca.cnt[1] = NIN;
    ca.s[2] = v;  ca.pf[2] = inv_d;            ca.cnt[2] = NIN;
    ca.s[3] = Wq; ca.pf[3] = w_d;              ca.cnt[3] = NW;
    ca.s[4] = Wk; ca.pf[4] = w_d + WSTRIDE;    ca.cnt[4] = NW;
    ca.s[5] = Wv; ca.pf[5] = w_d + 2*WSTRIDE;  ca.cnt[5] = NW;
    ca.s[6] = Wo; ca.pf[6] = w_d + 3*WSTRIDE;  ca.cnt[6] = NW;
    cvt_planes7<<<dim3((NIN + 255) / 256, 1, 7), 256>>>(ca);

    const int smem_gemm = 3 * GSTAGE_B;                 // 61440
    cudaFuncSetAttribute(gemm_planes, cudaFuncAttributeMaxDynamicSharedMemorySize, smem_gemm);
    const int smem_attn = 3 * ASTG + 64 * 4;            // 55552
    cudaFuncSetAttribute(attn_mma, cudaFuncAttributeMaxDynamicSharedMemorySize, smem_attn);

    GP aq{inq_d, w_d, bq, nullptr, qf_d, QSCALE};
    GP ak{ink_d, w_d + WSTRIDE, bk, nullptr, kf_d, 1.f};
    GP av{inv_d, w_d + 2 * WSTRIDE, bv, nullptr, vf_d, 1.f};
    gemm_planes<<<dim3(ND / 128, MROWS / 128, 3), 256, smem_gemm>>>(aq, ak, av, 1);

    attn_mma<<<dim3(NS / 128, NB * NH, NSPLIT), 256, smem_attn>>>(
        qf_d, kf_d, vf_d, mask, pO_d, pml_d);

    attn_combine<<<1024, 256>>>(pO_d, pml_d, cf_d);

    GP ao{cf_d, w_d + 3 * WSTRIDE, bo, out, nullptr, 1.f};
    gemm_planes<<<dim3(ND / 128, MROWS / 128, 1), 256, smem_gemm>>>(ao, ao, ao, 0);
}